// round 16
// baseline (speedup 1.0000x reference)
#include <cuda_runtime.h>
#include <cuda_bf16.h>
#include <math.h>
#include <stdint.h>

#define Nn 131072
#define Bg 16
#define Cc 128
#define Kk 16
#define TILE 128           // pool tile
#define MT   64            // mlp node tile (2 per CTA)
#define EPSF 1e-9f

// d_out layout: out[B,K,C], s[N,K], mu[B,K,2], losses[9]
#define OUT_POOL_OFF 0
#define S_OFF        (Bg*Kk*Cc)
#define MU_OFF       (S_OFF + Nn*Kk)
#define LOSS_OFF     (MU_OFF + Bg*Kk*2)

// ---- K1 (mlp) smem ----
#define OPST 272
#define A_BYTES (MT*OPST)                   // 17408
#define B_BYTES (128*OPST)                  // 34816
#define SM_AHI  0
#define SM_ALO  A_BYTES                     // 17408
#define SM_BHI  (2*A_BYTES)                 // 34816 (W1 hi, persistent)
#define SM_BLO  (SM_BHI + B_BYTES)          // 69632 (W1 lo, persistent)
#define SM_LARR (SM_BLO + B_BYTES)          // 104448, f32[64*17] = 4352
#define SM_B1   (SM_LARR + MT*17*4)         // 108800
#define SM_B2   (SM_B1 + 512)               // 109312
#define SM_MSK  (SM_B2 + 64)                // 109376
#define SM_ENT  (SM_MSK + 64)               // 109440
#define SMEM1   (SM_ENT + 128)              // 109568 -> 2 CTAs/SM, 32 warps
// logits partials overlay on the dead A region
#define SM_LP   SM_AHI
#define LP_WORDS 1088

// ---- K3 (pool) smem ----
#define P_XS   0
#define P_SS   (128*132*4)
#define P_PSM  (P_SS + TILE*17*4)
#define P_BVAL (P_PSM + 1024)
#define SMEM3  (P_BVAL + 512)               // 77824 -> 2 CTAs/SM (512 thr -> 32 warps/SM)

// scratch
__device__ float g_sum_s[Bg*Kk];
__device__ float g_sum_pos[Bg*Kk*2];
__device__ float g_ent;
__device__ __align__(16) char g_w1t[2*B_BYTES];   // preconverted W1 hi||lo

// ---------------- helpers ----------------
__device__ __forceinline__ uint32_t smem_u32(const void* p) {
    uint32_t a;
    asm("{ .reg .u64 t; cvta.to.shared.u64 t, %1; cvt.u32.u64 %0, t; }"
        : "=r"(a) : "l"(p));
    return a;
}
__device__ __forceinline__ void ldsm_x4(uint32_t* r, uint32_t addr) {
    asm volatile("ldmatrix.sync.aligned.m8n8.x4.shared.b16 {%0,%1,%2,%3}, [%4];"
                 : "=r"(r[0]), "=r"(r[1]), "=r"(r[2]), "=r"(r[3]) : "r"(addr));
}
__device__ __forceinline__ void mma16816(float* c, const uint32_t* a,
                                         uint32_t b0, uint32_t b1) {
    asm volatile("mma.sync.aligned.m16n8k16.row.col.f32.bf16.bf16.f32 "
        "{%0,%1,%2,%3}, {%4,%5,%6,%7}, {%8,%9}, {%0,%1,%2,%3};"
        : "+f"(c[0]), "+f"(c[1]), "+f"(c[2]), "+f"(c[3])
        : "r"(a[0]), "r"(a[1]), "r"(a[2]), "r"(a[3]), "r"(b0), "r"(b1));
}
__device__ __forceinline__ void cvt_store2(char* hi_b, char* lo_b, int off,
                                           float f0, float f1) {
    __nv_bfloat16 h0 = __float2bfloat16(f0);
    __nv_bfloat16 h1 = __float2bfloat16(f1);
    __nv_bfloat16 l0 = __float2bfloat16(f0 - __bfloat162float(h0));
    __nv_bfloat16 l1 = __float2bfloat16(f1 - __bfloat162float(h1));
    uint32_t hp = (uint32_t)__bfloat16_as_ushort(h0) | ((uint32_t)__bfloat16_as_ushort(h1) << 16);
    uint32_t lp = (uint32_t)__bfloat16_as_ushort(l0) | ((uint32_t)__bfloat16_as_ushort(l1) << 16);
    *(uint32_t*)(hi_b + off) = hp;
    *(uint32_t*)(lo_b + off) = lp;
}

// ---------------- init: zero accumulators + preconvert W1 ----------------
__global__ void init_kernel(const float* __restrict__ W1,
                            float* __restrict__ out_pool) {
    int idx = blockIdx.x * blockDim.x + threadIdx.x;
    if (idx < Bg*Kk*Cc) out_pool[idx] = 0.f;
    if (idx < 8192) {                         // 128 rows x 64 col-pairs
        int r = idx >> 6, cp = idx & 63;
        int c = cp * 2;
        float f0 = W1[r * Cc + c], f1 = W1[r * Cc + c + 1];
        cvt_store2(g_w1t, g_w1t + B_BYTES, r * OPST + c * 2, f0, f1);
    }
    if (blockIdx.x == 0) {
        int t = threadIdx.x;
        if (t < Bg*Kk) g_sum_s[t] = 0.f;
        for (int i = t; i < Bg*Kk*2; i += blockDim.x) g_sum_pos[i] = 0.f;
        if (t == 0) g_ent = 0.f;
    }
}

// ---------------- K1: MLP, 2x64-node tiles/CTA, 512 threads, 2 CTAs/SM (R15) ----------------
extern "C" __global__ void __launch_bounds__(512, 2)
mlp_kernel(const float* __restrict__ x,
           const float* __restrict__ gumbel,
           const float* __restrict__ b1,
           const float* __restrict__ W2,
           const float* __restrict__ b2,
           const float* __restrict__ scaling_p,
           const float* __restrict__ amask,
           float* __restrict__ s_out)
{
    extern __shared__ char smc[];
    float* larr = (float*)(smc + SM_LARR);
    float* b1s  = (float*)(smc + SM_B1);
    float* b2s  = (float*)(smc + SM_B2);
    float* msk  = (float*)(smc + SM_MSK);
    float* entacc = (float*)(smc + SM_ENT);
    float* lp   = (float*)(smc + SM_LP);    // [8][1088] overlay on dead A region

    const int tid  = threadIdx.x;
    const int wid = tid >> 5, lane = tid & 31;
    const float sc = __ldg(scaling_p);
    const uint32_t sbase = smem_u32(smc);

    // ---- one-time: W1 preconverted image copy (hi||lo, 4352 x 16B) ----
    {
        const uint4* src = (const uint4*)g_w1t;
        uint4* dst = (uint4*)(smc + SM_BHI);
        for (int i = tid; i < (2*B_BYTES)/16; i += 512)
            dst[i] = src[i];
    }
    if (tid < Cc) b1s[tid] = b1[tid];
    if (tid < Kk) { b2s[tid] = b2[tid]; msk[tid] = amask[tid]; }
    if (tid == 0) entacc[0] = 0.f;

    const int wm = wid & 1, wn = wid >> 1;
    const uint32_t a_base = sbase + SM_AHI
        + (uint32_t)((wm*32 + (lane & 15)) * OPST + (lane >> 4) * 16);
    const uint32_t b_base = sbase + SM_BHI
        + (uint32_t)((wn*16 + (lane & 7) + ((lane >> 4) & 1)*8) * OPST
                     + ((lane >> 3) & 1) * 16);
    const int qr = lane >> 2, qc = lane & 3;

    #pragma unroll 1
    for (int t = 0; t < 2; t++) {
        const int base = blockIdx.x * (2*MT) + t * MT;

        // ---- x tile (64 rows) load + bf16 hi/lo conversion (overwrites lp) ----
        for (int r = wid; r < MT; r += 16) {
            float4 v = ((const float4*)(x + (size_t)(base + r) * Cc))[lane];
            int off = r * OPST + lane * 8;
            cvt_store2(smc + SM_AHI, smc + SM_ALO, off,     v.x, v.y);
            cvt_store2(smc + SM_AHI, smc + SM_ALO, off + 4, v.z, v.w);
        }
        __syncthreads();

        // ---- GEMM via HMMA: 2x8 warp grid, each m32 x n16, k=128 ----
        float c[2][2][4];
        #pragma unroll
        for (int i = 0; i < 2; i++)
            #pragma unroll
            for (int nb = 0; nb < 2; nb++)
                #pragma unroll
                for (int q = 0; q < 4; q++) c[i][nb][q] = 0.f;

        #pragma unroll 2
        for (int ks = 0; ks < 8; ks++) {
            const uint32_t koff = ks * 32;
            uint32_t ah[2][4], al[2][4], bh[4], bl[4];
            #pragma unroll
            for (int i = 0; i < 2; i++) {
                ldsm_x4(ah[i], a_base + i*(16*OPST) + koff);
                ldsm_x4(al[i], a_base + A_BYTES + i*(16*OPST) + koff);
            }
            ldsm_x4(bh, b_base + koff);
            ldsm_x4(bl, b_base + B_BYTES + koff);
            #pragma unroll
            for (int i = 0; i < 2; i++) {
                mma16816(c[i][0], ah[i], bh[0], bh[1]);
                mma16816(c[i][0], ah[i], bl[0], bl[1]);
                mma16816(c[i][0], al[i], bh[0], bh[1]);
                mma16816(c[i][1], ah[i], bh[2], bh[3]);
                mma16816(c[i][1], ah[i], bl[2], bl[3]);
                mma16816(c[i][1], al[i], bh[2], bh[3]);
            }
        }
        __syncthreads();   // all warps done reading A before lp overlay on A

        // ---- epilogue in registers: +b1, relu ----
        #pragma unroll
        for (int nb = 0; nb < 2; nb++) {
            const int col = wn*16 + nb*8 + qc*2;
            const float bc0 = b1s[col], bc1 = b1s[col+1];
            #pragma unroll
            for (int i = 0; i < 2; i++) {
                float v0 = c[i][nb][0] + bc0, v1 = c[i][nb][1] + bc1;
                float v2 = c[i][nb][2] + bc0, v3 = c[i][nb][3] + bc1;
                c[i][nb][0] = v0 > 0.f ? v0 : 0.f;
                c[i][nb][1] = v1 > 0.f ? v1 : 0.f;
                c[i][nb][2] = v2 > 0.f ? v2 : 0.f;
                c[i][nb][3] = v3 > 0.f ? v3 : 0.f;
            }
        }

        // ---- logits from fragments: contract, shfl-reduce, store partials to lp ----
        {
            const int cbase = wn*16 + qc*2;
            float* lpw = lp + wn * LP_WORDS;
            #pragma unroll 4
            for (int k = 0; k < Kk; k++) {
                float2 w0 = __ldg((const float2*)(W2 + (size_t)k * Cc + cbase));
                float2 w1 = __ldg((const float2*)(W2 + (size_t)k * Cc + cbase + 8));
                float pr[4];
                #pragma unroll
                for (int i = 0; i < 2; i++) {
                    pr[i*2+0] = c[i][0][0]*w0.x + c[i][0][1]*w0.y
                              + c[i][1][0]*w1.x + c[i][1][1]*w1.y;
                    pr[i*2+1] = c[i][0][2]*w0.x + c[i][0][3]*w0.y
                              + c[i][1][2]*w1.x + c[i][1][3]*w1.y;
                }
                #pragma unroll
                for (int p = 0; p < 4; p++) {
                    pr[p] += __shfl_xor_sync(0xffffffffu, pr[p], 1);
                    pr[p] += __shfl_xor_sync(0xffffffffu, pr[p], 2);
                }
                if (qc == 0) {
                    #pragma unroll
                    for (int p = 0; p < 4; p++) {
                        const int row = wm*32 + (p >> 1)*16 + (p & 1)*8 + qr;
                        lpw[row*17 + k] = pr[p];
                    }
                }
            }
        }
        __syncthreads();

        // ---- fold 8 wn-partials + b2, scale -> larr ----
        for (int idx = tid; idx < MT*Kk; idx += 512) {
            const int r = idx >> 4, k = idx & 15;
            float s = b2s[k];
            #pragma unroll
            for (int w = 0; w < 8; w++) s += lp[w*LP_WORDS + r*17 + k];
            larr[r*17 + k] = s * sc;
        }
        __syncthreads();

        // ---- gumbel softmax + entropy + s output (64 threads) ----
        if (tid < MT) {
            const int n = tid;
            float gv[16];
            const float4* gp = (const float4*)(gumbel + (size_t)(base + n) * Kk);
            #pragma unroll
            for (int q = 0; q < 4; q++) {
                float4 g = gp[q];
                gv[q*4+0]=g.x; gv[q*4+1]=g.y; gv[q*4+2]=g.z; gv[q*4+3]=g.w;
            }
            float z[16];
            float mx = -3.4e38f;
            #pragma unroll
            for (int k = 0; k < Kk; k++) {
                float l = larr[n*17 + k];
                if (msk[k] == 0.f) l = -1e9f;
                z[k] = l + gv[k];
                mx = fmaxf(mx, z[k]);
            }
            float sum = 0.f;
            #pragma unroll
            for (int k = 0; k < Kk; k++) { z[k] = __expf(z[k] - mx); sum += z[k]; }
            float inv = 1.f / sum;
            float ent = 0.f;
            float so[16];
            #pragma unroll
            for (int k = 0; k < Kk; k++) {
                float sv = z[k] * inv;
                so[k] = sv;
                ent += sv * __logf(sv + EPSF);
            }
            float4* sp = (float4*)(s_out + (size_t)(base + n) * Kk);
            #pragma unroll
            for (int q = 0; q < 4; q++)
                sp[q] = make_float4(so[q*4], so[q*4+1], so[q*4+2], so[q*4+3]);
            atomicAdd(entacc, ent);
        }
        __syncthreads();   // lp/larr reads done; A region free for next tile
    }
    if (tid == 0) atomicAdd(&g_ent, entacc[0]);
}

// ---------------- K3: pooling, 512 threads (node-split), 2 CTAs/SM ----------------
extern "C" __global__ void __launch_bounds__(512, 2)
pool_kernel(const float* __restrict__ x,
            const int* __restrict__ batch,
            const float* __restrict__ pos,
            const float* __restrict__ s_in,
            float* __restrict__ out_pool)
{
    extern __shared__ char smc[];
    float* xs   = (float*)(smc + P_XS);
    float* ss   = (float*)(smc + P_SS);
    float* psm  = (float*)(smc + P_PSM);
    int*   bval = (int*)(smc + P_BVAL);

    const int tid  = threadIdx.x;
    const int base = blockIdx.x * TILE;
    const int wid = tid >> 5, lane = tid & 31;

    for (int r = wid; r < TILE; r += 16) {
        float4 v = ((const float4*)(x + (size_t)(base + r) * Cc))[lane];
        *(float4*)(xs + r * 132 + lane * 4) = v;
    }
    for (int idx = tid; idx < TILE*4; idx += 512) {
        const int r = idx >> 2, q = idx & 3;
        float4 v = ((const float4*)(s_in + (size_t)(base + r) * Kk))[q];
        ss[r*17 + q*4 + 0] = v.x;  ss[r*17 + q*4 + 1] = v.y;
        ss[r*17 + q*4 + 2] = v.z;  ss[r*17 + q*4 + 3] = v.w;
    }
    if (tid < TILE) {
        int bv = batch[base + tid];
        bval[tid] = bv < 0 ? 0 : (bv >= Bg ? Bg - 1 : bv);
        psm[tid*2]   = pos[(size_t)(base + tid)*2];
        psm[tid*2+1] = pos[(size_t)(base + tid)*2 + 1];
    }
    __syncthreads();

    const int b_lo = bval[0], b_hi = bval[TILE-1];
    const int kk  = tid & 15;
    const int cg  = (tid >> 4) & 15;
    const int grp = tid >> 8;            // 0/1 -> nodes [grp*64, grp*64+64)
    const int n0  = grp * 64;
    for (int b = b_lo; b <= b_hi; ++b) {
        float4 r0 = make_float4(0.f,0.f,0.f,0.f), r1 = r0;
        float ssum = 0.f, p0 = 0.f, p1 = 0.f;
        #pragma unroll 4
        for (int nn = 0; nn < 64; nn++) {
            const int n = n0 + nn;
            if (bval[n] == b) {
                float sv = ss[n*17 + kk];
                float4 xa = *(const float4*)(xs + n*132 + cg*8);
                float4 xb = *(const float4*)(xs + n*132 + cg*8 + 4);
                r0.x += sv*xa.x; r0.y += sv*xa.y; r0.z += sv*xa.z; r0.w += sv*xa.w;
                r1.x += sv*xb.x; r1.y += sv*xb.y; r1.z += sv*xb.z; r1.w += sv*xb.w;
                if (cg == 0) {
                    ssum += sv;
                    p0 += sv * psm[n*2];
                    p1 += sv * psm[n*2+1];
                }
            }
        }
        float* op = out_pool + ((size_t)(b*Kk + kk)) * Cc + cg*8;
        atomicAdd(op + 0, r0.x); atomicAdd(op + 1, r0.y);
        atomicAdd(op + 2, r0.z); atomicAdd(op + 3, r0.w);
        atomicAdd(op + 4, r1.x); atomicAdd(op + 5, r1.y);
        atomicAdd(op + 6, r1.z); atomicAdd(op + 7, r1.w);
        if (cg == 0) {
            atomicAdd(&g_sum_s[b*Kk + kk], ssum);
            atomicAdd(&g_sum_pos[(b*Kk + kk)*2],     p0);
            atomicAdd(&g_sum_pos[(b*Kk + kk)*2 + 1], p1);
        }
    }
}

// ---------------- finalize (R12, unchanged) ----------------
__global__ void finalize_kernel(const float* __restrict__ amask,
                                float* __restrict__ out)
{
    __shared__ float avg[Kk];
    __shared__ float mu_s[Bg*Kk*2];
    __shared__ float sepacc;
    const int tid = threadIdx.x;
    if (tid == 0) sepacc = 0.f;
    if (tid < Kk) {
        float s = 0.f;
        for (int b = 0; b < Bg; b++) s += g_sum_s[b*Kk + tid];
        avg[tid] = s / (float)Nn;
    }
    for (int i = tid; i < Bg*Kk*2; i += blockDim.x) {
        int bk = i >> 1;
        float m = g_sum_pos[i] / (g_sum_s[bk] + EPSF);
        mu_s[i] = m;
        out[MU_OFF + i] = m;
    }
    __syncthreads();

    float rep = 0.f;
    for (int i = tid; i < Bg*Kk*Kk; i += blockDim.x) {
        int b = i >> 8, r = i & 255, j = r >> 4, k = r & 15;
        if (j != k) {
            float dx = mu_s[(b*Kk + j)*2]     - mu_s[(b*Kk + k)*2];
            float dy = mu_s[(b*Kk + j)*2 + 1] - mu_s[(b*Kk + k)*2 + 1];
            rep += 1.f / (dx*dx + dy*dy + 1.f);
        }
    }
    #pragma unroll
    for (int off = 16; off; off >>= 1) rep += __shfl_down_sync(0xffffffffu, rep, off);
    if ((tid & 31) == 0) atomicAdd(&sepacc, rep);
    __syncthreads();

    if (tid == 0) {
        const float up = 1.f / (float)Kk;
        float entropy = -g_ent / (float)Nn;
        float div = 0.f, prun = 0.f, msum = 0.f, col = 0.f, mean = 0.f;
        for (int k = 0; k < Kk; k++) {
            div  += up * logf(up / (avg[k] + EPSF));
            prun += fabsf(avg[k] * (1.f - amask[k]));
            msum += amask[k];
            float d = avg[k] - up;
            col  += d * d;
            mean += avg[k];
        }
        prun /= (float)Kk;
        float sparsity = (msum / (float)Kk) * 0.01f;
        col *= 2.0f;
        mean /= (float)Kk;
        float var = 0.f;
        for (int k = 0; k < Kk; k++) { float d = avg[k] - mean; var += d * d; }
        var /= (float)Kk;
        float bal = sqrtf(var);
        float sep = sepacc / (float)(Kk * (Kk - 1));
        float* L = out + LOSS_OFF;
        L[0] = entropy; L[1] = div; L[2] = 0.f; L[3] = prun; L[4] = sparsity;
        L[5] = 0.f;     L[6] = col; L[7] = bal; L[8] = sep;
    }
}

extern "C" void kernel_launch(void* const* d_in, const int* in_sizes, int n_in,
                              void* d_out, int out_size)
{
    const float* x     = (const float*)d_in[0];
    const int*   batch = (const int*)d_in[1];
    const float* pos   = (const float*)d_in[2];
    const float* gum   = (const float*)d_in[3];
    const float* W1    = (const float*)d_in[4];
    const float* b1    = (const float*)d_in[5];
    const float* W2    = (const float*)d_in[6];
    const float* b2    = (const float*)d_in[7];
    const float* scal  = (const float*)d_in[8];
    const float* amask = (const float*)d_in[9];
    float* out = (float*)d_out;

    cudaFuncSetAttribute(mlp_kernel,
                         cudaFuncAttributeMaxDynamicSharedMemorySize, SMEM1);
    cudaFuncSetAttribute(pool_kernel,
                         cudaFuncAttributeMaxDynamicSharedMemorySize, SMEM3);

    init_kernel<<<(Bg*Kk*Cc + 255)/256, 256>>>(W1, out + OUT_POOL_OFF);
    mlp_kernel<<<Nn / (2*MT), 512, SMEM1>>>(
        x, gum, b1, W2, b2, scal, amask, out + S_OFF);
    pool_kernel<<<Nn / TILE, 512, SMEM3>>>(
        x, batch, pos, out + S_OFF, out + OUT_POOL_OFF);
    finalize_kernel<<<1, 256>>>(amask, out);
}

// round 17
// speedup vs baseline: 1.6267x; 1.6267x over previous
#include <cuda_runtime.h>
#include <cuda_bf16.h>
#include <math.h>
#include <stdint.h>

#define Nn 131072
#define Bg 16
#define Cc 128
#define Kk 16
#define TILE 128           // pool tile
#define MT   64            // mlp node tile (2 per CTA)
#define EPSF 1e-9f

// d_out layout: out[B,K,C], s[N,K], mu[B,K,2], losses[9]
#define OUT_POOL_OFF 0
#define S_OFF        (Bg*Kk*Cc)
#define MU_OFF       (S_OFF + Nn*Kk)
#define LOSS_OFF     (MU_OFF + Bg*Kk*2)

// ---- K1 (mlp) smem ----
#define OPST 272
#define A_BYTES (MT*OPST)                   // 17408
#define B_BYTES (128*OPST)                  // 34816
#define SM_AHI  0
#define SM_ALO  A_BYTES                     // 17408
#define SM_BHI  (2*A_BYTES)                 // 34816 (W1 hi, persistent)
#define SM_BLO  (SM_BHI + B_BYTES)          // 69632 (W1 lo, persistent)
#define SM_LARR (SM_BLO + B_BYTES)          // 104448, f32[64*17] = 4352
#define SM_B1   (SM_LARR + MT*17*4)         // 108800
#define SM_B2   (SM_B1 + 512)               // 109312
#define SM_MSK  (SM_B2 + 64)                // 109376
#define SM_ENT  (SM_MSK + 64)               // 109440
#define SMEM1   (SM_ENT + 128)              // 109568 -> 2 CTAs/SM, 32 warps
// logits partials overlay on the dead A region
#define SM_LP   SM_AHI
#define LP_WORDS 1088

// ---- K3 (pool) smem ----
#define P_XS   0
#define P_SS   (128*132*4)
#define P_PSM  (P_SS + TILE*17*4)
#define P_BVAL (P_PSM + 1024)
#define SMEM3  (P_BVAL + 512)               // 77824 -> 2 CTAs/SM

// scratch
__device__ float g_sum_s[Bg*Kk];
__device__ float g_sum_pos[Bg*Kk*2];
__device__ float g_ent;
__device__ __align__(16) char g_w1t[2*B_BYTES];   // preconverted W1 hi||lo

// ---------------- helpers ----------------
__device__ __forceinline__ uint32_t smem_u32(const void* p) {
    uint32_t a;
    asm("{ .reg .u64 t; cvta.to.shared.u64 t, %1; cvt.u32.u64 %0, t; }"
        : "=r"(a) : "l"(p));
    return a;
}
__device__ __forceinline__ void ldsm_x4(uint32_t* r, uint32_t addr) {
    asm volatile("ldmatrix.sync.aligned.m8n8.x4.shared.b16 {%0,%1,%2,%3}, [%4];"
                 : "=r"(r[0]), "=r"(r[1]), "=r"(r[2]), "=r"(r[3]) : "r"(addr));
}
__device__ __forceinline__ void mma16816(float* c, const uint32_t* a,
                                         uint32_t b0, uint32_t b1) {
    asm volatile("mma.sync.aligned.m16n8k16.row.col.f32.bf16.bf16.f32 "
        "{%0,%1,%2,%3}, {%4,%5,%6,%7}, {%8,%9}, {%0,%1,%2,%3};"
        : "+f"(c[0]), "+f"(c[1]), "+f"(c[2]), "+f"(c[3])
        : "r"(a[0]), "r"(a[1]), "r"(a[2]), "r"(a[3]), "r"(b0), "r"(b1));
}
__device__ __forceinline__ void cvt_store2(char* hi_b, char* lo_b, int off,
                                           float f0, float f1) {
    __nv_bfloat16 h0 = __float2bfloat16(f0);
    __nv_bfloat16 h1 = __float2bfloat16(f1);
    __nv_bfloat16 l0 = __float2bfloat16(f0 - __bfloat162float(h0));
    __nv_bfloat16 l1 = __float2bfloat16(f1 - __bfloat162float(h1));
    uint32_t hp = (uint32_t)__bfloat16_as_ushort(h0) | ((uint32_t)__bfloat16_as_ushort(h1) << 16);
    uint32_t lp = (uint32_t)__bfloat16_as_ushort(l0) | ((uint32_t)__bfloat16_as_ushort(l1) << 16);
    *(uint32_t*)(hi_b + off) = hp;
    *(uint32_t*)(lo_b + off) = lp;
}

// ---------------- init: zero accumulators + preconvert W1 ----------------
__global__ void init_kernel(const float* __restrict__ W1,
                            float* __restrict__ out_pool) {
    int idx = blockIdx.x * blockDim.x + threadIdx.x;
    if (idx < Bg*Kk*Cc) out_pool[idx] = 0.f;
    if (idx < 8192) {                         // 128 rows x 64 col-pairs
        int r = idx >> 6, cp = idx & 63;
        int c = cp * 2;
        float f0 = W1[r * Cc + c], f1 = W1[r * Cc + c + 1];
        cvt_store2(g_w1t, g_w1t + B_BYTES, r * OPST + c * 2, f0, f1);
    }
    if (blockIdx.x == 0) {
        int t = threadIdx.x;
        if (t < Bg*Kk) g_sum_s[t] = 0.f;
        for (int i = t; i < Bg*Kk*2; i += blockDim.x) g_sum_pos[i] = 0.f;
        if (t == 0) g_ent = 0.f;
    }
}

// ---------------- K1: MLP, 2x64-node tiles/CTA, 512 threads, 2 CTAs/SM ----------------
extern "C" __global__ void __launch_bounds__(512, 2)
mlp_kernel(const float* __restrict__ x,
           const float* __restrict__ gumbel,
           const float* __restrict__ b1,
           const float* __restrict__ W2,
           const float* __restrict__ b2,
           const float* __restrict__ scaling_p,
           const float* __restrict__ amask,
           float* __restrict__ s_out)
{
    extern __shared__ char smc[];
    float* larr = (float*)(smc + SM_LARR);
    float* b1s  = (float*)(smc + SM_B1);
    float* b2s  = (float*)(smc + SM_B2);
    float* msk  = (float*)(smc + SM_MSK);
    float* entacc = (float*)(smc + SM_ENT);
    float* lp   = (float*)(smc + SM_LP);    // [8][1088] overlay on dead A region

    const int tid  = threadIdx.x;
    const int wid = tid >> 5, lane = tid & 31;
    const float sc = __ldg(scaling_p);
    const uint32_t sbase = smem_u32(smc);

    // ---- one-time: W1 preconverted image copy (hi||lo, 4352 x 16B) ----
    {
        const uint4* src = (const uint4*)g_w1t;
        uint4* dst = (uint4*)(smc + SM_BHI);
        for (int i = tid; i < (2*B_BYTES)/16; i += 512)
            dst[i] = src[i];
    }
    if (tid < Cc) b1s[tid] = b1[tid];
    if (tid < Kk) { b2s[tid] = b2[tid]; msk[tid] = amask[tid]; }
    if (tid == 0) entacc[0] = 0.f;

    // ---- preload tile 0 x (64 rows) + bf16 hi/lo conversion ----
    {
        const int base0 = blockIdx.x * (2*MT);
        for (int r = wid; r < MT; r += 16) {
            float4 v = ((const float4*)(x + (size_t)(base0 + r) * Cc))[lane];
            int off = r * OPST + lane * 8;
            cvt_store2(smc + SM_AHI, smc + SM_ALO, off,     v.x, v.y);
            cvt_store2(smc + SM_AHI, smc + SM_ALO, off + 4, v.z, v.w);
        }
    }
    __syncthreads();

    const int wm = wid & 1, wn = wid >> 1;
    const uint32_t a_base = sbase + SM_AHI
        + (uint32_t)((wm*32 + (lane & 15)) * OPST + (lane >> 4) * 16);
    const uint32_t b_base = sbase + SM_BHI
        + (uint32_t)((wn*16 + (lane & 7) + ((lane >> 4) & 1)*8) * OPST
                     + ((lane >> 3) & 1) * 16);
    const int qr = lane >> 2, qc = lane & 3;

    #pragma unroll 1
    for (int t = 0; t < 2; t++) {
        const int base = blockIdx.x * (2*MT) + t * MT;

        // ---- GEMM via HMMA: 2x8 warp grid, each m32 x n16, k=128 ----
        float c[2][2][4];
        #pragma unroll
        for (int i = 0; i < 2; i++)
            #pragma unroll
            for (int nb = 0; nb < 2; nb++)
                #pragma unroll
                for (int q = 0; q < 4; q++) c[i][nb][q] = 0.f;

        #pragma unroll 2
        for (int ks = 0; ks < 8; ks++) {
            const uint32_t koff = ks * 32;
            uint32_t ah[2][4], al[2][4], bh[4], bl[4];
            #pragma unroll
            for (int i = 0; i < 2; i++) {
                ldsm_x4(ah[i], a_base + i*(16*OPST) + koff);
                ldsm_x4(al[i], a_base + A_BYTES + i*(16*OPST) + koff);
            }
            ldsm_x4(bh, b_base + koff);
            ldsm_x4(bl, b_base + B_BYTES + koff);
            #pragma unroll
            for (int i = 0; i < 2; i++) {
                mma16816(c[i][0], ah[i], bh[0], bh[1]);
                mma16816(c[i][0], ah[i], bl[0], bl[1]);
                mma16816(c[i][0], al[i], bh[0], bh[1]);
                mma16816(c[i][1], ah[i], bh[2], bh[3]);
                mma16816(c[i][1], ah[i], bl[2], bl[3]);
                mma16816(c[i][1], al[i], bh[2], bh[3]);
            }
        }
        __syncthreads();   // all warps done reading A before lp overlay on A

        // ---- epilogue in registers: +b1, relu ----
        #pragma unroll
        for (int nb = 0; nb < 2; nb++) {
            const int col = wn*16 + nb*8 + qc*2;
            const float bc0 = b1s[col], bc1 = b1s[col+1];
            #pragma unroll
            for (int i = 0; i < 2; i++) {
                float v0 = c[i][nb][0] + bc0, v1 = c[i][nb][1] + bc1;
                float v2 = c[i][nb][2] + bc0, v3 = c[i][nb][3] + bc1;
                c[i][nb][0] = v0 > 0.f ? v0 : 0.f;
                c[i][nb][1] = v1 > 0.f ? v1 : 0.f;
                c[i][nb][2] = v2 > 0.f ? v2 : 0.f;
                c[i][nb][3] = v3 > 0.f ? v3 : 0.f;
            }
        }

        // ---- logits from fragments: contract, shfl-reduce, store partials to lp ----
        {
            const int cbase = wn*16 + qc*2;
            float* lpw = lp + wn * LP_WORDS;
            #pragma unroll 4
            for (int k = 0; k < Kk; k++) {
                float2 w0 = __ldg((const float2*)(W2 + (size_t)k * Cc + cbase));
                float2 w1 = __ldg((const float2*)(W2 + (size_t)k * Cc + cbase + 8));
                float pr[4];
                #pragma unroll
                for (int i = 0; i < 2; i++) {
                    pr[i*2+0] = c[i][0][0]*w0.x + c[i][0][1]*w0.y
                              + c[i][1][0]*w1.x + c[i][1][1]*w1.y;
                    pr[i*2+1] = c[i][0][2]*w0.x + c[i][0][3]*w0.y
                              + c[i][1][2]*w1.x + c[i][1][3]*w1.y;
                }
                #pragma unroll
                for (int p = 0; p < 4; p++) {
                    pr[p] += __shfl_xor_sync(0xffffffffu, pr[p], 1);
                    pr[p] += __shfl_xor_sync(0xffffffffu, pr[p], 2);
                }
                if (qc == 0) {
                    #pragma unroll
                    for (int p = 0; p < 4; p++) {
                        const int row = wm*32 + (p >> 1)*16 + (p & 1)*8 + qr;
                        lpw[row*17 + k] = pr[p];
                    }
                }
            }
        }
        __syncthreads();

        // ---- fold 8 wn-partials + b2, scale -> larr ----
        for (int idx = tid; idx < MT*Kk; idx += 512) {
            const int r = idx >> 4, k = idx & 15;
            float s = b2s[k];
            #pragma unroll
            for (int w = 0; w < 8; w++) s += lp[w*LP_WORDS + r*17 + k];
            larr[r*17 + k] = s * sc;
        }
        __syncthreads();   // lp consumed; A region now free

        // ---- softmax (warps 0-1) OVERLAPPED with next-tile x load (warps 2-15) ----
        if (tid < MT) {
            const int n = tid;
            float gv[16];
            const float4* gp = (const float4*)(gumbel + (size_t)(base + n) * Kk);
            #pragma unroll
            for (int q = 0; q < 4; q++) {
                float4 g = gp[q];
                gv[q*4+0]=g.x; gv[q*4+1]=g.y; gv[q*4+2]=g.z; gv[q*4+3]=g.w;
            }
            float z[16];
            float mx = -3.4e38f;
            #pragma unroll
            for (int k = 0; k < Kk; k++) {
                float l = larr[n*17 + k];
                if (msk[k] == 0.f) l = -1e9f;
                z[k] = l + gv[k];
                mx = fmaxf(mx, z[k]);
            }
            float sum = 0.f;
            #pragma unroll
            for (int k = 0; k < Kk; k++) { z[k] = __expf(z[k] - mx); sum += z[k]; }
            float inv = 1.f / sum;
            float ent = 0.f;
            float so[16];
            #pragma unroll
            for (int k = 0; k < Kk; k++) {
                float sv = z[k] * inv;
                so[k] = sv;
                ent += sv * __logf(sv + EPSF);
            }
            float4* sp = (float4*)(s_out + (size_t)(base + n) * Kk);
            #pragma unroll
            for (int q = 0; q < 4; q++)
                sp[q] = make_float4(so[q*4], so[q*4+1], so[q*4+2], so[q*4+3]);
            atomicAdd(entacc, ent);
        } else if (t == 0 && wid >= 2) {
            // warps 2..15 (14 warps) load tile 1 into the free A region
            const int base1 = blockIdx.x * (2*MT) + MT;
            for (int r = wid - 2; r < MT; r += 14) {
                float4 v = ((const float4*)(x + (size_t)(base1 + r) * Cc))[lane];
                int off = r * OPST + lane * 8;
                cvt_store2(smc + SM_AHI, smc + SM_ALO, off,     v.x, v.y);
                cvt_store2(smc + SM_AHI, smc + SM_ALO, off + 4, v.z, v.w);
            }
        }
        __syncthreads();   // softmax done reading larr; tile-1 A ready for next GEMM
    }
    if (tid == 0) atomicAdd(&g_ent, entacc[0]);
}

// ---------------- K3: pooling (R15/R12, 256 threads, unchanged) ----------------
extern "C" __global__ void __launch_bounds__(256, 2)
pool_kernel(const float* __restrict__ x,
            const int* __restrict__ batch,
            const float* __restrict__ pos,
            const float* __restrict__ s_in,
            float* __restrict__ out_pool)
{
    extern __shared__ char smc[];
    float* xs   = (float*)(smc + P_XS);
    float* ss   = (float*)(smc + P_SS);
    float* psm  = (float*)(smc + P_PSM);
    int*   bval = (int*)(smc + P_BVAL);

    const int tid  = threadIdx.x;
    const int base = blockIdx.x * TILE;
    const int wid = tid >> 5, lane = tid & 31;

    for (int r = wid; r < TILE; r += 8) {
        float4 v = ((const float4*)(x + (size_t)(base + r) * Cc))[lane];
        *(float4*)(xs + r * 132 + lane * 4) = v;
    }
    for (int idx = tid; idx < TILE*4; idx += 256) {
        const int r = idx >> 2, q = idx & 3;
        float4 v = ((const float4*)(s_in + (size_t)(base + r) * Kk))[q];
        ss[r*17 + q*4 + 0] = v.x;  ss[r*17 + q*4 + 1] = v.y;
        ss[r*17 + q*4 + 2] = v.z;  ss[r*17 + q*4 + 3] = v.w;
    }
    if (tid < TILE) {
        int bv = batch[base + tid];
        bval[tid] = bv < 0 ? 0 : (bv >= Bg ? Bg - 1 : bv);
        psm[tid*2]   = pos[(size_t)(base + tid)*2];
        psm[tid*2+1] = pos[(size_t)(base + tid)*2 + 1];
    }
    __syncthreads();

    const int b_lo = bval[0], b_hi = bval[TILE-1];
    const int kk = tid & 15;
    const int cg = tid >> 4;
    for (int b = b_lo; b <= b_hi; ++b) {
        float4 r0 = make_float4(0.f,0.f,0.f,0.f), r1 = r0;
        float ssum = 0.f, p0 = 0.f, p1 = 0.f;
        #pragma unroll 4
        for (int n = 0; n < TILE; n++) {
            if (bval[n] == b) {
                float sv = ss[n*17 + kk];
                float4 xa = *(const float4*)(xs + n*132 + cg*8);
                float4 xb = *(const float4*)(xs + n*132 + cg*8 + 4);
                r0.x += sv*xa.x; r0.y += sv*xa.y; r0.z += sv*xa.z; r0.w += sv*xa.w;
                r1.x += sv*xb.x; r1.y += sv*xb.y; r1.z += sv*xb.z; r1.w += sv*xb.w;
                if (cg == 0) {
                    ssum += sv;
                    p0 += sv * psm[n*2];
                    p1 += sv * psm[n*2+1];
                }
            }
        }
        float* op = out_pool + ((size_t)(b*Kk + kk)) * Cc + cg*8;
        atomicAdd(op + 0, r0.x); atomicAdd(op + 1, r0.y);
        atomicAdd(op + 2, r0.z); atomicAdd(op + 3, r0.w);
        atomicAdd(op + 4, r1.x); atomicAdd(op + 5, r1.y);
        atomicAdd(op + 6, r1.z); atomicAdd(op + 7, r1.w);
        if (cg == 0) {
            atomicAdd(&g_sum_s[b*Kk + kk], ssum);
            atomicAdd(&g_sum_pos[(b*Kk + kk)*2],     p0);
            atomicAdd(&g_sum_pos[(b*Kk + kk)*2 + 1], p1);
        }
    }
}

// ---------------- finalize (unchanged) ----------------
__global__ void finalize_kernel(const float* __restrict__ amask,
                                float* __restrict__ out)
{
    __shared__ float avg[Kk];
    __shared__ float mu_s[Bg*Kk*2];
    __shared__ float sepacc;
    const int tid = threadIdx.x;
    if (tid == 0) sepacc = 0.f;
    if (tid < Kk) {
        float s = 0.f;
        for (int b = 0; b < Bg; b++) s += g_sum_s[b*Kk + tid];
        avg[tid] = s / (float)Nn;
    }
    for (int i = tid; i < Bg*Kk*2; i += blockDim.x) {
        int bk = i >> 1;
        float m = g_sum_pos[i] / (g_sum_s[bk] + EPSF);
        mu_s[i] = m;
        out[MU_OFF + i] = m;
    }
    __syncthreads();

    float rep = 0.f;
    for (int i = tid; i < Bg*Kk*Kk; i += blockDim.x) {
        int b = i >> 8, r = i & 255, j = r >> 4, k = r & 15;
        if (j != k) {
            float dx = mu_s[(b*Kk + j)*2]     - mu_s[(b*Kk + k)*2];
            float dy = mu_s[(b*Kk + j)*2 + 1] - mu_s[(b*Kk + k)*2 + 1];
            rep += 1.f / (dx*dx + dy*dy + 1.f);
        }
    }
    #pragma unroll
    for (int off = 16; off; off >>= 1) rep += __shfl_down_sync(0xffffffffu, rep, off);
    if ((tid & 31) == 0) atomicAdd(&sepacc, rep);
    __syncthreads();

    if (tid == 0) {
        const float up = 1.f / (float)Kk;
        float entropy = -g_ent / (float)Nn;
        float div = 0.f, prun = 0.f, msum = 0.f, col = 0.f, mean = 0.f;
        for (int k = 0; k < Kk; k++) {
            div  += up * logf(up / (avg[k] + EPSF));
            prun += fabsf(avg[k] * (1.f - amask[k]));
            msum += amask[k];
            float d = avg[k] - up;
            col  += d * d;
            mean += avg[k];
        }
        prun /= (float)Kk;
        float sparsity = (msum / (float)Kk) * 0.01f;
        col *= 2.0f;
        mean /= (float)Kk;
        float var = 0.f;
        for (int k = 0; k < Kk; k++) { float d = avg[k] - mean; var += d * d; }
        var /= (float)Kk;
        float bal = sqrtf(var);
        float sep = sepacc / (float)(Kk * (Kk - 1));
        float* L = out + LOSS_OFF;
        L[0] = entropy; L[1] = div; L[2] = 0.f; L[3] = prun; L[4] = sparsity;
        L[5] = 0.f;     L[6] = col; L[7] = bal; L[8] = sep;
    }
}

extern "C" void kernel_launch(void* const* d_in, const int* in_sizes, int n_in,
                              void* d_out, int out_size)
{
    const float* x     = (const float*)d_in[0];
    const int*   batch = (const int*)d_in[1];
    const float* pos   = (const float*)d_in[2];
    const float* gum   = (const float*)d_in[3];
    const float* W1    = (const float*)d_in[4];
    const float* b1    = (const float*)d_in[5];
    const float* W2    = (const float*)d_in[6];
    const float* b2    = (const float*)d_in[7];
    const float* scal  = (const float*)d_in[8];
    const float* amask = (const float*)d_in[9];
    float* out = (float*)d_out;

    cudaFuncSetAttribute(mlp_kernel,
                         cudaFuncAttributeMaxDynamicSharedMemorySize, SMEM1);
    cudaFuncSetAttribute(pool_kernel,
                         cudaFuncAttributeMaxDynamicSharedMemorySize, SMEM3);

    init_kernel<<<(Bg*Kk*Cc + 255)/256, 256>>>(W1, out + OUT_POOL_OFF);
    mlp_kernel<<<Nn / (2*MT), 512, SMEM1>>>(
        x, gum, b1, W2, b2, scal, amask, out + S_OFF);
    pool_kernel<<<Nn / TILE, 256, SMEM3>>>(
        x, batch, pos, out + S_OFF, out + OUT_POOL_OFF);
    finalize_kernel<<<1, 256>>>(amask, out);
}